// round 9
// baseline (speedup 1.0000x reference)
#include <cuda_runtime.h>
#include <cstdint>

#define NT 1024   // 32 warps, one block, one SM: 8 warps per scheduler

using u64 = unsigned long long;

__device__ __forceinline__ u64 pk(float lo, float hi) {
    u64 r; asm("mov.b64 %0, {%1,%2};" : "=l"(r) : "f"(lo), "f"(hi)); return r;
}
__device__ __forceinline__ void upk(u64 p, float& lo, float& hi) {
    asm("mov.b64 {%0,%1}, %2;" : "=f"(lo), "=f"(hi) : "l"(p));
}
__device__ __forceinline__ u64 fma2(u64 a, u64 b, u64 c) {
    u64 d; asm("fma.rn.f32x2 %0, %1, %2, %3;" : "=l"(d) : "l"(a), "l"(b), "l"(c)); return d;
}
__device__ __forceinline__ u64 mul2(u64 a, u64 b) {
    u64 d; asm("mul.rn.f32x2 %0, %1, %2;" : "=l"(d) : "l"(a), "l"(b)); return d;
}
__device__ __forceinline__ float frcp(float x) {
    float r; asm("rcp.approx.f32 %0, %1;" : "=f"(r) : "f"(x)); return r;
}
__device__ __forceinline__ float flg2(float x) {
    float r; asm("lg2.approx.f32 %0, %1;" : "=f"(r) : "f"(x)); return r;
}
__device__ __forceinline__ float fsqrt_ap(float x) {
    float r; asm("sqrt.approx.f32 %0, %1;" : "=f"(r) : "f"(x)); return r;
}

__global__ void __launch_bounds__(NT, 1)
sgd_filter_design_kernel(const float* __restrict__ sos_init,
                         const float* __restrict__ target_dB,
                         float* __restrict__ out)
{
    // coefficient-major state: cof[c][s]; adjacent sections form 8B pairs
    __shared__ __align__(16) float cof[6][16];
    // trig packed as ADJACENT freq pairs: tc1p[j] = (c1_{2j}, c1_{2j+1}), etc.
    __shared__ __align__(8) u64 tc1p[256], ts1p[256], tc2p[256], ts2p[256];
    __shared__ __align__(8) float pcc[512];   // plain cc array (u64 view = adjacent pairs)
    __shared__ float part[2][96];             // two half-range partials per parameter

    const int tid  = threadIdx.x;
    const int warp = tid >> 5;
    const int lane = tid & 31;
    const int freq = tid >> 1;                // 2 threads per frequency
    const int h    = tid & 1;                 // section half: h*8 .. h*8+7

    if (tid < 96) cof[tid % 6][tid / 6] = sos_init[tid];

    // Per-thread trig for its frequency (double precision once).
    float tc1, ts1, tc2, ts2, tgt;
    {
        double w = (double)freq * (3.14159265358979323846 / 511.0);
        tc1 = (float)cos(w);        ts1 = (float)sin(w);
        tc2 = (float)cos(2.0 * w);  ts2 = (float)sin(2.0 * w);
        tgt = target_dB[freq];
        if (h == 0) {
            int j = freq >> 1, e = freq & 1;
            ((float*)&tc1p[j])[e] = tc1;  ((float*)&ts1p[j])[e] = ts1;
            ((float*)&tc2p[j])[e] = tc2;  ((float*)&ts2p[j])[e] = ts2;
        }
    }
    const u64 pc1 = pk(tc1, tc1), ps1 = pk(ts1, ts1);
    const u64 pc2 = pk(tc2, tc2), ps2 = pk(ts2, ts2);
    __syncthreads();

    const float KC  = 40.0f / (512.0f * 2.30258509299404568402f); // 2/n * 20/ln10
    const float DB2 = 6.02059991327962390427f;                    // 20*log10(2)
    const float EPS = 1e-8f;
    const float LR  = 0.1f;

    const u64* cofp = (const u64*)cof;        // row c = cofp[c*8 .. c*8+7]
    const u64* pccp = (const u64*)pcc;

    const int s2 = warp >> 1;                 // pass-2 section for this warp
    const int hf = warp & 1;                  // pass-2 frequency half

    for (int it = 0; it < 1000; ++it) {
        // ---------- Pass 1: thread handles 8 sections (its half) for its freq;
        // ratio per 4-section group; thread-pair combine via shfl.
        u64 accR = pk(1.0f, 1.0f);
#pragma unroll
        for (int p = 0; p < 2; ++p) {
            int i0 = h * 4 + 2 * p;
            u64 prodB, prodA;
            {
                u64 b0 = cofp[0*8+i0], b1 = cofp[1*8+i0], b2 = cofp[2*8+i0];
                u64 a0 = cofp[3*8+i0], a1 = cofp[4*8+i0], a2 = cofp[5*8+i0];
                u64 Br = fma2(b2, pc2, fma2(b1, pc1, b0));
                u64 Bp = fma2(b2, ps2, mul2(b1, ps1));
                u64 Ar = fma2(a2, pc2, fma2(a1, pc1, a0));
                u64 Ap = fma2(a2, ps2, mul2(a1, ps1));
                prodB = fma2(Bp, Bp, mul2(Br, Br));
                prodA = fma2(Ap, Ap, mul2(Ar, Ar));
            }
            {
                u64 b0 = cofp[0*8+i0+1], b1 = cofp[1*8+i0+1], b2 = cofp[2*8+i0+1];
                u64 a0 = cofp[3*8+i0+1], a1 = cofp[4*8+i0+1], a2 = cofp[5*8+i0+1];
                u64 Br = fma2(b2, pc2, fma2(b1, pc1, b0));
                u64 Bp = fma2(b2, ps2, mul2(b1, ps1));
                u64 Ar = fma2(a2, pc2, fma2(a1, pc1, a0));
                u64 Ap = fma2(a2, ps2, mul2(a1, ps1));
                prodB = mul2(prodB, fma2(Bp, Bp, mul2(Br, Br)));
                prodA = mul2(prodA, fma2(Ap, Ap, mul2(Ar, Ar)));
            }
            float al, ah; upk(prodA, al, ah);
            accR = mul2(accR, mul2(prodB, pk(frcp(al), frcp(ah))));
        }
        {
            float rlo, rhi; upk(accR, rlo, rhi);
            float myp = rlo * rhi;                         // 8-section ratio
            myp *= __shfl_xor_sync(0xffffffffu, myp, 1);   // combine halves -> |H|^2
            if (h == 0) {
                float mag = fsqrt_ap(myp);
                float mpe = mag + EPS;
                float dB  = DB2 * flg2(mpe);
                pcc[freq] = KC * (dB - tgt) * (mag * frcp(mpe));
            }
        }
        __syncthreads();

        // ---------- Pass 2: warp (s2, hf) integrates section s2 over 256 freqs
        {
            float sb0 = cof[0][s2], sb1 = cof[1][s2], sb2 = cof[2][s2];
            float sa0 = cof[3][s2], sa1 = cof[4][s2], sa2 = cof[5][s2];
            u64 b0 = pk(sb0, sb0), b1 = pk(sb1, sb1), b2 = pk(sb2, sb2);
            u64 a0 = pk(sa0, sa0), a1 = pk(sa1, sa1), a2 = pk(sa2, sa2);
            u64 G0 = 0, G1 = 0, G2 = 0, H3 = 0, H4 = 0, H5 = 0;
#pragma unroll
            for (int k = 0; k < 4; ++k) {
                int j = hf * 128 + k * 32 + lane;   // packed freq-pair index
                u64 c1 = tc1p[j], s1 = ts1p[j];
                u64 c2 = tc2p[j], s2v = ts2p[j];
                u64 cc = pccp[j];
                u64 Br = fma2(b2, c2, fma2(b1, c1, b0));
                u64 Bp = fma2(b2, s2v, mul2(b1, s1));
                u64 Ar = fma2(a2, c2, fma2(a1, c1, a0));
                u64 Ap = fma2(a2, s2v, mul2(a1, s1));
                u64 nB = fma2(Bp, Bp, mul2(Br, Br));
                u64 nA = fma2(Ap, Ap, mul2(Ar, Ar));
                u64 prod = mul2(nB, nA);
                float pl, ph; upk(prod, pl, ph);
                u64 ccr = mul2(cc, pk(frcp(pl), frcp(ph)));
                u64 cB = mul2(ccr, nA);            // cc/|B|^2
                u64 cA = mul2(ccr, nB);            // cc/|A|^2 (negate later)
                G0 = fma2(cB, Br, G0);
                G1 = fma2(cB, fma2(s1, Bp, mul2(c1, Br)), G1);
                G2 = fma2(cB, fma2(s2v, Bp, mul2(c2, Br)), G2);
                H3 = fma2(cA, Ar, H3);
                H4 = fma2(cA, fma2(s1, Ap, mul2(c1, Ar)), H4);
                H5 = fma2(cA, fma2(s2v, Ap, mul2(c2, Ar)), H5);
            }
            float g0, g1, g2, g3, g4, g5, u, v;
            upk(G0, u, v); g0 = u + v;
            upk(G1, u, v); g1 = u + v;
            upk(G2, u, v); g2 = u + v;
            upk(H3, u, v); g3 = -(u + v);
            upk(H4, u, v); g4 = -(u + v);
            upk(H5, u, v); g5 = -(u + v);
#pragma unroll
            for (int o = 16; o > 0; o >>= 1) {
                g0 += __shfl_xor_sync(0xffffffffu, g0, o);
                g1 += __shfl_xor_sync(0xffffffffu, g1, o);
                g2 += __shfl_xor_sync(0xffffffffu, g2, o);
                g3 += __shfl_xor_sync(0xffffffffu, g3, o);
                g4 += __shfl_xor_sync(0xffffffffu, g4, o);
                g5 += __shfl_xor_sync(0xffffffffu, g5, o);
            }
            if (lane < 6) {
                float gsel = g0;
                if (lane == 1) gsel = g1;
                if (lane == 2) gsel = g2;
                if (lane == 3) gsel = g3;
                if (lane == 4) gsel = g4;
                if (lane == 5) gsel = g5;
                part[hf][s2 * 6 + lane] = gsel;
            }
        }
        __syncthreads();

        // ---------- SGD update (fixed order) ----------
        if (tid < 96) cof[tid % 6][tid / 6] -= LR * (part[0][tid] + part[1][tid]);
        __syncthreads();
    }

    if (tid < 96) out[tid] = cof[tid % 6][tid / 6];
}

extern "C" void kernel_launch(void* const* d_in, const int* in_sizes, int n_in,
                              void* d_out, int out_size) {
    const float* sos_init  = (const float*)d_in[0];   // [16,6] = 96 floats
    const float* target_dB = (const float*)d_in[1];   // [512]
    float* out = (float*)d_out;                       // [16,6] = 96 floats
    sgd_filter_design_kernel<<<1, NT>>>(sos_init, target_dB, out);
}

// round 10
// speedup vs baseline: 1.5084x; 1.5084x over previous
#include <cuda_runtime.h>
#include <cstdint>

#define NT      512   // threads per CTA (16 warps)
#define CLUSTER 2     // 2 CTAs; 256 freqs each

using u64 = unsigned long long;

__device__ __forceinline__ u64 pk(float lo, float hi) {
    u64 r; asm("mov.b64 %0, {%1,%2};" : "=l"(r) : "f"(lo), "f"(hi)); return r;
}
__device__ __forceinline__ void upk(u64 p, float& lo, float& hi) {
    asm("mov.b64 {%0,%1}, %2;" : "=f"(lo), "=f"(hi) : "l"(p));
}
__device__ __forceinline__ u64 fma2(u64 a, u64 b, u64 c) {
    u64 d; asm("fma.rn.f32x2 %0, %1, %2, %3;" : "=l"(d) : "l"(a), "l"(b), "l"(c)); return d;
}
__device__ __forceinline__ u64 mul2(u64 a, u64 b) {
    u64 d; asm("mul.rn.f32x2 %0, %1, %2;" : "=l"(d) : "l"(a), "l"(b)); return d;
}
__device__ __forceinline__ float frcp(float x) {
    float r; asm("rcp.approx.f32 %0, %1;" : "=f"(r) : "f"(x)); return r;
}
__device__ __forceinline__ float flg2(float x) {
    float r; asm("lg2.approx.f32 %0, %1;" : "=f"(r) : "f"(x)); return r;
}
__device__ __forceinline__ float fsqrt_ap(float x) {
    float r; asm("sqrt.approx.f32 %0, %1;" : "=f"(r) : "f"(x)); return r;
}
__device__ __forceinline__ uint32_t smem_u32(const void* p) {
    uint32_t a;
    asm("{ .reg .u64 t; cvta.to.shared.u64 t, %1; cvt.u32.u64 %0, t; }" : "=r"(a) : "l"(p));
    return a;
}
__device__ __forceinline__ uint32_t my_rank() {
    uint32_t r; asm("mov.u32 %0, %%cluster_ctarank;" : "=r"(r)); return r;
}
__device__ __forceinline__ void st_cluster_f32(uint32_t local_addr, uint32_t rank, float v) {
    uint32_t remote;
    asm volatile("mapa.shared::cluster.u32 %0, %1, %2;" : "=r"(remote) : "r"(local_addr), "r"(rank));
    asm volatile("st.shared::cluster.f32 [%0], %1;" :: "r"(remote), "f"(v) : "memory");
}
__device__ __forceinline__ void cluster_sync() {
    asm volatile("barrier.cluster.arrive.aligned;" ::: "memory");  // release
    asm volatile("barrier.cluster.wait.aligned;" ::: "memory");    // acquire
}

__global__ void __launch_bounds__(NT, 1) __cluster_dims__(CLUSTER, 1, 1)
sgd_filter_design_kernel(const float* __restrict__ sos_init,
                         const float* __restrict__ target_dB,
                         float* __restrict__ out)
{
    // coefficient-major state (replicated): cof[c][s]; adjacent sections = 8B pairs
    __shared__ __align__(16) float cof[6][16];
    // local 256 freqs packed as adjacent pairs: tc1p[j] = (c1_{2j}, c1_{2j+1})
    __shared__ __align__(8) u64 tc1p[128], ts1p[128], tc2p[128], ts2p[128];
    __shared__ __align__(8) float pcc[256];        // local per-freq weights
    __shared__ float part[2][CLUSTER][96];         // [buf][srcRank][param]

    const int tid  = threadIdx.x;
    const int warp = tid >> 5;
    const int lane = tid & 31;
    const int fl   = tid >> 1;                // local freq 0..255
    const int h    = tid & 1;                 // section half: h*8 .. h*8+7
    const uint32_t rank = my_rank();
    const uint32_t peer = rank ^ 1u;

    if (tid < 96) cof[tid % 6][tid / 6] = sos_init[tid];

    // Per-thread trig for its local frequency (double precision once).
    float tc1, ts1, tc2, ts2, tgt;
    {
        int gf = (int)rank * 256 + fl;
        double w = (double)gf * (3.14159265358979323846 / 511.0);
        tc1 = (float)cos(w);        ts1 = (float)sin(w);
        tc2 = (float)cos(2.0 * w);  ts2 = (float)sin(2.0 * w);
        tgt = target_dB[gf];
        if (h == 0) {
            int j = fl >> 1, e = fl & 1;
            ((float*)&tc1p[j])[e] = tc1;  ((float*)&ts1p[j])[e] = ts1;
            ((float*)&tc2p[j])[e] = tc2;  ((float*)&ts2p[j])[e] = ts2;
        }
    }
    const u64 pc1 = pk(tc1, tc1), ps1 = pk(ts1, ts1);
    const u64 pc2 = pk(tc2, tc2), ps2 = pk(ts2, ts2);
    __syncthreads();
    cluster_sync();   // both CTAs initialized before any DSMEM traffic

    const float KC  = 40.0f / (512.0f * 2.30258509299404568402f); // 2/n * 20/ln10
    const float DB2 = 6.02059991327962390427f;                    // 20*log10(2)
    const float EPS = 1e-8f;
    const float LR  = 0.1f;

    const u64* cofp = (const u64*)cof;        // row c = cofp[c*8 .. c*8+7]
    const u64* pccp = (const u64*)pcc;

    for (int it = 0; it < 1000; ++it) {
        const int buf = it & 1;

        // ---------- Pass 1: thread = (local freq, section half); packed pairs;
        // ratio per 4-section group (bounded range), halves combined via shfl.
        u64 accR = pk(1.0f, 1.0f);
#pragma unroll
        for (int p = 0; p < 2; ++p) {
            int i0 = h * 4 + 2 * p;
            u64 prodB, prodA;
            {
                u64 b0 = cofp[0*8+i0], b1 = cofp[1*8+i0], b2 = cofp[2*8+i0];
                u64 a0 = cofp[3*8+i0], a1 = cofp[4*8+i0], a2 = cofp[5*8+i0];
                u64 Br = fma2(b2, pc2, fma2(b1, pc1, b0));
                u64 Bp = fma2(b2, ps2, mul2(b1, ps1));   // = -Im(B)
                u64 Ar = fma2(a2, pc2, fma2(a1, pc1, a0));
                u64 Ap = fma2(a2, ps2, mul2(a1, ps1));
                prodB = fma2(Bp, Bp, mul2(Br, Br));
                prodA = fma2(Ap, Ap, mul2(Ar, Ar));
            }
            {
                u64 b0 = cofp[0*8+i0+1], b1 = cofp[1*8+i0+1], b2 = cofp[2*8+i0+1];
                u64 a0 = cofp[3*8+i0+1], a1 = cofp[4*8+i0+1], a2 = cofp[5*8+i0+1];
                u64 Br = fma2(b2, pc2, fma2(b1, pc1, b0));
                u64 Bp = fma2(b2, ps2, mul2(b1, ps1));
                u64 Ar = fma2(a2, pc2, fma2(a1, pc1, a0));
                u64 Ap = fma2(a2, ps2, mul2(a1, ps1));
                prodB = mul2(prodB, fma2(Bp, Bp, mul2(Br, Br)));
                prodA = mul2(prodA, fma2(Ap, Ap, mul2(Ar, Ar)));
            }
            float al, ah; upk(prodA, al, ah);
            accR = mul2(accR, mul2(prodB, pk(frcp(al), frcp(ah))));
        }
        {
            float rlo, rhi; upk(accR, rlo, rhi);
            float myp = rlo * rhi;                         // 8-section ratio
            myp *= __shfl_xor_sync(0xffffffffu, myp, 1);   // combine halves -> |H|^2
            if (h == 0) {
                float mag = fsqrt_ap(myp);
                float mpe = mag + EPS;
                float dB  = DB2 * flg2(mpe);
                pcc[fl] = KC * (dB - tgt) * (mag * frcp(mpe));
            }
        }
        __syncthreads();

        // ---------- Pass 2: warp s integrates section s over local 256 freqs ----
        {
            const int s = warp;
            float sb0 = cof[0][s], sb1 = cof[1][s], sb2 = cof[2][s];
            float sa0 = cof[3][s], sa1 = cof[4][s], sa2 = cof[5][s];
            u64 b0 = pk(sb0, sb0), b1 = pk(sb1, sb1), b2 = pk(sb2, sb2);
            u64 a0 = pk(sa0, sa0), a1 = pk(sa1, sa1), a2 = pk(sa2, sa2);
            u64 G0 = 0, G1 = 0, G2 = 0, H3 = 0, H4 = 0, H5 = 0;
#pragma unroll
            for (int k = 0; k < 4; ++k) {
                int j = k * 32 + lane;              // packed freq-pair index
                u64 c1 = tc1p[j], s1 = ts1p[j];
                u64 c2 = tc2p[j], s2v = ts2p[j];
                u64 cc = pccp[j];
                u64 Br = fma2(b2, c2, fma2(b1, c1, b0));
                u64 Bp = fma2(b2, s2v, mul2(b1, s1));
                u64 Ar = fma2(a2, c2, fma2(a1, c1, a0));
                u64 Ap = fma2(a2, s2v, mul2(a1, s1));
                u64 nB = fma2(Bp, Bp, mul2(Br, Br));
                u64 nA = fma2(Ap, Ap, mul2(Ar, Ar));
                u64 prod = mul2(nB, nA);            // one rcp serves both norms
                float pl, ph; upk(prod, pl, ph);
                u64 ccr = mul2(cc, pk(frcp(pl), frcp(ph)));
                u64 cB = mul2(ccr, nA);             // cc/|B|^2
                u64 cA = mul2(ccr, nB);             // cc/|A|^2 (negate later)
                G0 = fma2(cB, Br, G0);
                G1 = fma2(cB, fma2(s1, Bp, mul2(c1, Br)), G1);
                G2 = fma2(cB, fma2(s2v, Bp, mul2(c2, Br)), G2);
                H3 = fma2(cA, Ar, H3);
                H4 = fma2(cA, fma2(s1, Ap, mul2(c1, Ar)), H4);
                H5 = fma2(cA, fma2(s2v, Ap, mul2(c2, Ar)), H5);
            }
            float g0, g1, g2, g3, g4, g5, u, v;
            upk(G0, u, v); g0 = u + v;
            upk(G1, u, v); g1 = u + v;
            upk(G2, u, v); g2 = u + v;
            upk(H3, u, v); g3 = -(u + v);
            upk(H4, u, v); g4 = -(u + v);
            upk(H5, u, v); g5 = -(u + v);
#pragma unroll
            for (int o = 16; o > 0; o >>= 1) {
                g0 += __shfl_xor_sync(0xffffffffu, g0, o);
                g1 += __shfl_xor_sync(0xffffffffu, g1, o);
                g2 += __shfl_xor_sync(0xffffffffu, g2, o);
                g3 += __shfl_xor_sync(0xffffffffu, g3, o);
                g4 += __shfl_xor_sync(0xffffffffu, g4, o);
                g5 += __shfl_xor_sync(0xffffffffu, g5, o);
            }
            // lanes 0..5 publish this CTA's partial locally AND to the peer
            if (lane < 6) {
                float gsel = g0;
                if (lane == 1) gsel = g1;
                if (lane == 2) gsel = g2;
                if (lane == 3) gsel = g3;
                if (lane == 4) gsel = g4;
                if (lane == 5) gsel = g5;
                part[buf][rank][s * 6 + lane] = gsel;
                uint32_t addr = smem_u32(&part[buf][rank][s * 6 + lane]);
                st_cluster_f32(addr, peer, gsel);
            }
        }
        // release-arrive orders the cluster stores; wait acquires peer's stores
        cluster_sync();

        // ---------- fused SGD update: warp s updates its own section ----------
        if (lane < 6) {
            int s = warp;
            float gr = part[buf][0][s * 6 + lane] + part[buf][1][s * 6 + lane];
            cof[lane][s] -= LR * gr;
        }
        __syncthreads();
    }

    if (rank == 0 && tid < 96) out[tid] = cof[tid % 6][tid / 6];
    cluster_sync();   // no CTA exits while the peer may still write its smem
}

extern "C" void kernel_launch(void* const* d_in, const int* in_sizes, int n_in,
                              void* d_out, int out_size) {
    const float* sos_init  = (const float*)d_in[0];   // [16,6] = 96 floats
    const float* target_dB = (const float*)d_in[1];   // [512]
    float* out = (float*)d_out;                       // [16,6] = 96 floats
    sgd_filter_design_kernel<<<CLUSTER, NT>>>(sos_init, target_dB, out);
}

// round 11
// speedup vs baseline: 2.1026x; 1.3939x over previous
#include <cuda_runtime.h>
#include <cstdint>

#define NT      512   // threads per CTA (16 warps)
#define CLUSTER 8     // 8 CTAs; 64 freqs each

using u64 = unsigned long long;

__device__ __forceinline__ u64 pk(float lo, float hi) {
    u64 r; asm("mov.b64 %0, {%1,%2};" : "=l"(r) : "f"(lo), "f"(hi)); return r;
}
__device__ __forceinline__ void upk(u64 p, float& lo, float& hi) {
    asm("mov.b64 {%0,%1}, %2;" : "=f"(lo), "=f"(hi) : "l"(p));
}
__device__ __forceinline__ u64 fma2(u64 a, u64 b, u64 c) {
    u64 d; asm("fma.rn.f32x2 %0, %1, %2, %3;" : "=l"(d) : "l"(a), "l"(b), "l"(c)); return d;
}
__device__ __forceinline__ u64 mul2(u64 a, u64 b) {
    u64 d; asm("mul.rn.f32x2 %0, %1, %2;" : "=l"(d) : "l"(a), "l"(b)); return d;
}
__device__ __forceinline__ float frcp(float x) {
    float r; asm("rcp.approx.f32 %0, %1;" : "=f"(r) : "f"(x)); return r;
}
__device__ __forceinline__ float flg2(float x) {
    float r; asm("lg2.approx.f32 %0, %1;" : "=f"(r) : "f"(x)); return r;
}
__device__ __forceinline__ float fsqrt_ap(float x) {
    float r; asm("sqrt.approx.f32 %0, %1;" : "=f"(r) : "f"(x)); return r;
}
__device__ __forceinline__ uint32_t smem_u32(const void* p) {
    uint32_t a;
    asm("{ .reg .u64 t; cvta.to.shared.u64 t, %1; cvt.u32.u64 %0, t; }" : "=r"(a) : "l"(p));
    return a;
}
__device__ __forceinline__ uint32_t my_rank() {
    uint32_t r; asm("mov.u32 %0, %%cluster_ctarank;" : "=r"(r)); return r;
}
__device__ __forceinline__ void st_cluster_f32(uint32_t local_addr, uint32_t rank, float v) {
    uint32_t remote;
    asm volatile("mapa.shared::cluster.u32 %0, %1, %2;" : "=r"(remote) : "r"(local_addr), "r"(rank));
    asm volatile("st.shared::cluster.f32 [%0], %1;" :: "r"(remote), "f"(v) : "memory");
}
__device__ __forceinline__ void cluster_sync() {
    asm volatile("barrier.cluster.arrive.aligned;" ::: "memory");  // release
    asm volatile("barrier.cluster.wait.aligned;" ::: "memory");    // acquire
}

__global__ void __launch_bounds__(NT, 1) __cluster_dims__(CLUSTER, 1, 1)
sgd_filter_design_kernel(const float* __restrict__ sos_init,
                         const float* __restrict__ target_dB,
                         float* __restrict__ out)
{
    // coefficient-major state (replicated): cof[c][s]; adjacent sections = 8B pairs
    __shared__ __align__(16) float cof[6][16];
    // local 64 freqs packed as adjacent pairs: tc1p[j] = (c1_{2j}, c1_{2j+1})
    __shared__ __align__(8) u64 tc1p[32], ts1p[32], tc2p[32], ts2p[32];
    __shared__ __align__(8) float pcc[64];         // local per-freq weights
    __shared__ float part[2][CLUSTER][96];         // [buf][srcRank][param]

    const int tid  = threadIdx.x;
    const int warp = tid >> 5;
    const int lane = tid & 31;
    const int fl   = tid >> 3;                // local freq 0..63 (8 threads each)
    const int h2   = tid & 7;                 // section-pair index: sections 2h2, 2h2+1
    const uint32_t rank = my_rank();

    if (tid < 96) cof[tid % 6][tid / 6] = sos_init[tid];

    // Per-thread trig for its local frequency (double precision once).
    float tc1, ts1, tc2, ts2, tgt;
    {
        int gf = (int)rank * 64 + fl;
        double w = (double)gf * (3.14159265358979323846 / 511.0);
        tc1 = (float)cos(w);        ts1 = (float)sin(w);
        tc2 = (float)cos(2.0 * w);  ts2 = (float)sin(2.0 * w);
        tgt = target_dB[gf];
        if (h2 == 0) {
            int j = fl >> 1, e = fl & 1;
            ((float*)&tc1p[j])[e] = tc1;  ((float*)&ts1p[j])[e] = ts1;
            ((float*)&tc2p[j])[e] = tc2;  ((float*)&ts2p[j])[e] = ts2;
        }
    }
    const u64 pc1 = pk(tc1, tc1), ps1 = pk(ts1, ts1);
    const u64 pc2 = pk(tc2, tc2), ps2 = pk(ts2, ts2);
    __syncthreads();
    cluster_sync();   // all CTAs initialized before any DSMEM traffic

    const float KC  = 40.0f / (512.0f * 2.30258509299404568402f); // 2/n * 20/ln10
    const float DB2 = 6.02059991327962390427f;                    // 20*log10(2)
    const float EPS = 1e-8f;
    const float LR  = 0.1f;

    const u64* cofp = (const u64*)cof;        // row c = cofp[c*8 .. c*8+7]
    const u64* pccp = (const u64*)pcc;

    for (int it = 0; it < 1000; ++it) {
        const int buf = it & 1;

        // ---------- Pass 1: thread = (freq fl, section pair h2); one packed
        // pair; ratio per pair; 8-thread shuffle-product combine.
        float myp;
        {
            u64 b0 = cofp[0*8+h2], b1 = cofp[1*8+h2], b2 = cofp[2*8+h2];
            u64 a0 = cofp[3*8+h2], a1 = cofp[4*8+h2], a2 = cofp[5*8+h2];
            u64 Br = fma2(b2, pc2, fma2(b1, pc1, b0));
            u64 Bp = fma2(b2, ps2, mul2(b1, ps1));   // = -Im(B)
            u64 Ar = fma2(a2, pc2, fma2(a1, pc1, a0));
            u64 Ap = fma2(a2, ps2, mul2(a1, ps1));
            u64 prodB = fma2(Bp, Bp, mul2(Br, Br));
            u64 prodA = fma2(Ap, Ap, mul2(Ar, Ar));
            float al, ah; upk(prodA, al, ah);
            u64 accR = mul2(prodB, pk(frcp(al), frcp(ah)));
            float rlo, rhi; upk(accR, rlo, rhi);
            myp = rlo * rhi;                           // 2-section ratio
            myp *= __shfl_xor_sync(0xffffffffu, myp, 1);
            myp *= __shfl_xor_sync(0xffffffffu, myp, 2);
            myp *= __shfl_xor_sync(0xffffffffu, myp, 4); // 16-section |H|^2
            if (h2 == 0) {
                float mag = fsqrt_ap(myp);
                float mpe = mag + EPS;
                float dB  = DB2 * flg2(mpe);
                pcc[fl] = KC * (dB - tgt) * (mag * frcp(mpe));
            }
        }
        __syncthreads();

        // ---------- Pass 2: warp s integrates section s over local 64 freqs
        // (single k-iteration: 32 packed pairs, lane j owns pair j).
        {
            const int s = warp;
            float sb0 = cof[0][s], sb1 = cof[1][s], sb2 = cof[2][s];
            float sa0 = cof[3][s], sa1 = cof[4][s], sa2 = cof[5][s];
            u64 b0 = pk(sb0, sb0), b1 = pk(sb1, sb1), b2 = pk(sb2, sb2);
            u64 a0 = pk(sa0, sa0), a1 = pk(sa1, sa1), a2 = pk(sa2, sa2);

            u64 c1 = tc1p[lane], s1 = ts1p[lane];
            u64 c2 = tc2p[lane], s2v = ts2p[lane];
            u64 cc = pccp[lane];
            u64 Br = fma2(b2, c2, fma2(b1, c1, b0));
            u64 Bp = fma2(b2, s2v, mul2(b1, s1));
            u64 Ar = fma2(a2, c2, fma2(a1, c1, a0));
            u64 Ap = fma2(a2, s2v, mul2(a1, s1));
            u64 nB = fma2(Bp, Bp, mul2(Br, Br));
            u64 nA = fma2(Ap, Ap, mul2(Ar, Ar));
            u64 prod = mul2(nB, nA);            // one rcp serves both norms
            float pl, ph; upk(prod, pl, ph);
            u64 ccr = mul2(cc, pk(frcp(pl), frcp(ph)));
            u64 cB = mul2(ccr, nA);             // cc/|B|^2
            u64 cA = mul2(ccr, nB);             // cc/|A|^2 (negate later)
            u64 G0 = mul2(cB, Br);
            u64 G1 = mul2(cB, fma2(s1, Bp, mul2(c1, Br)));
            u64 G2 = mul2(cB, fma2(s2v, Bp, mul2(c2, Br)));
            u64 H3 = mul2(cA, Ar);
            u64 H4 = mul2(cA, fma2(s1, Ap, mul2(c1, Ar)));
            u64 H5 = mul2(cA, fma2(s2v, Ap, mul2(c2, Ar)));

            float g0, g1, g2, g3, g4, g5, u, v;
            upk(G0, u, v); g0 = u + v;
            upk(G1, u, v); g1 = u + v;
            upk(G2, u, v); g2 = u + v;
            upk(H3, u, v); g3 = -(u + v);
            upk(H4, u, v); g4 = -(u + v);
            upk(H5, u, v); g5 = -(u + v);
#pragma unroll
            for (int o = 16; o > 0; o >>= 1) {
                g0 += __shfl_xor_sync(0xffffffffu, g0, o);
                g1 += __shfl_xor_sync(0xffffffffu, g1, o);
                g2 += __shfl_xor_sync(0xffffffffu, g2, o);
                g3 += __shfl_xor_sync(0xffffffffu, g3, o);
                g4 += __shfl_xor_sync(0xffffffffu, g4, o);
                g5 += __shfl_xor_sync(0xffffffffu, g5, o);
            }
            // lanes 0..5 broadcast this CTA's partial to all 8 CTAs (incl self)
            if (lane < 6) {
                float gsel = g0;
                if (lane == 1) gsel = g1;
                if (lane == 2) gsel = g2;
                if (lane == 3) gsel = g3;
                if (lane == 4) gsel = g4;
                if (lane == 5) gsel = g5;
                uint32_t addr = smem_u32(&part[buf][rank][s * 6 + lane]);
#pragma unroll
                for (int r = 0; r < CLUSTER; ++r)
                    st_cluster_f32(addr, (uint32_t)r, gsel);
            }
        }
        // release-arrive orders the cluster stores; wait acquires peers' stores
        cluster_sync();

        // ---------- fused SGD update: warp s updates its own section ----------
        if (lane < 6) {
            int idx = warp * 6 + lane;
            float gr = part[buf][0][idx];
#pragma unroll
            for (int r = 1; r < CLUSTER; ++r) gr += part[buf][r][idx];
            cof[lane][warp] -= LR * gr;
        }
        __syncthreads();
    }

    if (rank == 0 && tid < 96) out[tid] = cof[tid % 6][tid / 6];
    cluster_sync();   // no CTA exits while peers may still write its smem
}

extern "C" void kernel_launch(void* const* d_in, const int* in_sizes, int n_in,
                              void* d_out, int out_size) {
    const float* sos_init  = (const float*)d_in[0];   // [16,6] = 96 floats
    const float* target_dB = (const float*)d_in[1];   // [512]
    float* out = (float*)d_out;                       // [16,6] = 96 floats
    sgd_filter_design_kernel<<<CLUSTER, NT>>>(sos_init, target_dB, out);
}